// round 6
// baseline (speedup 1.0000x reference)
#include <cuda_runtime.h>
#include <cstdint>
#include <math.h>

#define T_SEQ 512
#define B_    64
#define H_    1024
#define G_    3072
#define L_    3
#define NBLK  128
#define KS    4
#define GPB   96
#define KPB   256
#define SMEMB ((96*260 + 64*260)*4)

__device__ float g_gx[(size_t)T_SEQ * B_ * G_];
__device__ float g_seqA[(size_t)T_SEQ * B_ * H_];
__device__ float g_seqB[(size_t)T_SEQ * B_ * H_];
__device__ float g_part[(size_t)KS * B_ * G_];
__device__ float g_h[B_ * H_];
__device__ unsigned g_bar;

__device__ __forceinline__ unsigned f2tf(float x) {
    unsigned u;
    asm("cvt.rna.tf32.f32 %0, %1;" : "=r"(u) : "f"(x));
    return u;
}

__device__ __forceinline__ void mma_tf32(float* c, const unsigned* a, const unsigned* b) {
    asm volatile(
        "mma.sync.aligned.m16n8k8.row.col.f32.tf32.tf32.f32 "
        "{%0,%1,%2,%3}, {%4,%5,%6,%7}, {%8,%9}, {%0,%1,%2,%3};"
        : "+f"(c[0]), "+f"(c[1]), "+f"(c[2]), "+f"(c[3])
        : "r"(a[0]), "r"(a[1]), "r"(a[2]), "r"(a[3]), "r"(b[0]), "r"(b[1]));
}

__device__ __forceinline__ void grid_barrier(unsigned target) {
    __syncthreads();
    if (threadIdx.x == 0) {
        asm volatile("red.release.gpu.add.u32 [%0], %1;" :: "l"(&g_bar), "r"(1u) : "memory");
        unsigned v;
        do {
            asm volatile("ld.acquire.gpu.u32 %0, [%1];" : "=r"(v) : "l"(&g_bar) : "memory");
        } while (v < target);
    }
    __syncthreads();
}

__global__ void reset_bar() { g_bar = 0u; }

// ---------------- input-gate GEMM: gx[m,g] = sum_k A[m,k]*W[g,k] + bias[g] ----------------
__global__ void __launch_bounds__(256, 2) gx_gemm(
    const float* __restrict__ Aext, int sel,
    const float* __restrict__ W, const float* __restrict__ bias)
{
    const float* A = (sel == 0) ? Aext : (sel == 1 ? g_seqA : g_seqB);
    float* out = g_gx;

    __shared__ unsigned As[16][136];
    __shared__ unsigned Bs[16][136];

    const int tid = threadIdx.x;
    const int mbase = blockIdx.y * 128, nbase = blockIdx.x * 128;
    const int lane = tid & 31, warp = tid >> 5;
    const int wm = (warp >> 2) * 64;   // 2 warps in M
    const int wn = (warp & 3) * 32;    // 4 warps in N
    const int q = lane & 3, g8 = lane >> 2;

    float acc[4][4][4];
#pragma unroll
    for (int i = 0; i < 4; i++)
#pragma unroll
        for (int j = 0; j < 4; j++)
#pragma unroll
            for (int k = 0; k < 4; k++) acc[i][j][k] = 0.f;

    for (int kt = 0; kt < H_; kt += 16) {
        __syncthreads();
#pragma unroll
        for (int r = 0; r < 2; r++) {
            int id = tid + r * 256;
            int row = id >> 2;
            int kc = (id & 3) << 2;
            float4 va = *(const float4*)(A + (size_t)(mbase + row) * H_ + kt + kc);
            As[kc + 0][row] = f2tf(va.x); As[kc + 1][row] = f2tf(va.y);
            As[kc + 2][row] = f2tf(va.z); As[kc + 3][row] = f2tf(va.w);
            float4 vb = *(const float4*)(W + (size_t)(nbase + row) * H_ + kt + kc);
            Bs[kc + 0][row] = f2tf(vb.x); Bs[kc + 1][row] = f2tf(vb.y);
            Bs[kc + 2][row] = f2tf(vb.z); Bs[kc + 3][row] = f2tf(vb.w);
        }
        __syncthreads();
#pragma unroll
        for (int ks = 0; ks < 16; ks += 8) {
            unsigned a[4][4], b[4][2];
#pragma unroll
            for (int mi = 0; mi < 4; mi++) {
                int m0 = wm + mi * 16 + g8;
                a[mi][0] = As[ks + q][m0];
                a[mi][1] = As[ks + q][m0 + 8];
                a[mi][2] = As[ks + 4 + q][m0];
                a[mi][3] = As[ks + 4 + q][m0 + 8];
            }
#pragma unroll
            for (int ni = 0; ni < 4; ni++) {
                int n0 = wn + ni * 8 + g8;
                b[ni][0] = Bs[ks + q][n0];
                b[ni][1] = Bs[ks + 4 + q][n0];
            }
#pragma unroll
            for (int mi = 0; mi < 4; mi++)
#pragma unroll
                for (int ni = 0; ni < 4; ni++)
                    mma_tf32(acc[mi][ni], a[mi], b[ni]);
        }
    }
#pragma unroll
    for (int mi = 0; mi < 4; mi++) {
        int m = mbase + wm + mi * 16 + g8;
#pragma unroll
        for (int ni = 0; ni < 4; ni++) {
            int n = nbase + wn + ni * 8 + 2 * q;
            float b0 = bias[n], b1 = bias[n + 1];
            *(float2*)(out + (size_t)m * G_ + n) =
                make_float2(acc[mi][ni][0] + b0, acc[mi][ni][1] + b1);
            *(float2*)(out + (size_t)(m + 8) * G_ + n) =
                make_float2(acc[mi][ni][2] + b0, acc[mi][ni][3] + b1);
        }
    }
}

// ---------------- persistent recurrence ----------------
extern __shared__ unsigned sh[];

__global__ void __launch_bounds__(256) recur(
    const float* __restrict__ Whh, const float* __restrict__ bhh,
    const float* __restrict__ h0, int outsel, float* __restrict__ hlast)
{
    unsigned (*Ws)[260] = (unsigned(*)[260])sh;
    unsigned (*hs)[260] = (unsigned(*)[260])(sh + 96 * 260);
    float* seqout = outsel ? g_seqB : g_seqA;

    const int tid = threadIdx.x, blk = blockIdx.x;
    const int grp = blk & 31, ksp = blk >> 5;
    const int lane = tid & 31, warp = tid >> 5;
    const int q = lane & 3, g8 = lane >> 2;
    const int wm = (warp >> 1) * 16;   // 4 warps in M (64)
    const int wn = (warp & 1) * 48;    // 2 warps in N (96)

    // Load W_hh slice -> SMEM (tf32), once
    const float* Wb = Whh + (size_t)(grp * GPB) * H_ + ksp * KPB;
#pragma unroll
    for (int it = 0; it < 24; it++) {
        int id = tid + it * 256;     // 0..6143 = 96 rows x 64 float4
        int r = id >> 6, c4 = id & 63;
        float4 v = *(const float4*)(Wb + (size_t)r * H_ + c4 * 4);
        uint4 u = make_uint4(f2tf(v.x), f2tf(v.y), f2tf(v.z), f2tf(v.w));
        *(uint4*)&Ws[r][c4 * 4] = u;
    }

    unsigned ph = 0;
    for (int t = 0; t < T_SEQ; t++) {
        // ---- phase A: stage h slice, GEMM partials ----
        const float* hsrc = (t == 0) ? h0 : g_h;
#pragma unroll
        for (int it = 0; it < 16; it++) {
            int id = tid + it * 256;  // 0..4095 = 64 rows x 64 float4
            int r = id >> 6, c4 = id & 63;
            float4 v = __ldcg((const float4*)(hsrc + (size_t)r * H_ + ksp * KPB + c4 * 4));
            uint4 u = make_uint4(f2tf(v.x), f2tf(v.y), f2tf(v.z), f2tf(v.w));
            *(uint4*)&hs[r][c4 * 4] = u;
        }
        __syncthreads();

        float acc[6][4];
#pragma unroll
        for (int ni = 0; ni < 6; ni++)
#pragma unroll
            for (int k = 0; k < 4; k++) acc[ni][k] = 0.f;

#pragma unroll 4
        for (int kt = 0; kt < KPB; kt += 8) {
            unsigned a[4];
            a[0] = hs[wm + g8][kt + q];
            a[1] = hs[wm + g8 + 8][kt + q];
            a[2] = hs[wm + g8][kt + q + 4];
            a[3] = hs[wm + g8 + 8][kt + q + 4];
#pragma unroll
            for (int ni = 0; ni < 6; ni++) {
                unsigned b[2];
                b[0] = Ws[wn + ni * 8 + g8][kt + q];
                b[1] = Ws[wn + ni * 8 + g8][kt + q + 4];
                mma_tf32(acc[ni], a, b);
            }
        }

        float* pp = g_part + (size_t)ksp * B_ * G_;
#pragma unroll
        for (int ni = 0; ni < 6; ni++) {
            int gcol = grp * GPB + wn + ni * 8 + 2 * q;
            int m0 = wm + g8;
            *(float2*)(pp + (size_t)m0 * G_ + gcol) = make_float2(acc[ni][0], acc[ni][1]);
            *(float2*)(pp + (size_t)(m0 + 8) * G_ + gcol) = make_float2(acc[ni][2], acc[ni][3]);
        }

        grid_barrier(++ph * NBLK);

        // ---- phase B: fused gates + h update ----
        {
            int idx = blk * 256 + tid;    // 0..32767 -> 2 elems each
            int b = idx >> 9;
            int j = (idx & 511) * 2;
            const float* gxt = g_gx + ((size_t)t * B_ + b) * G_;
            float2 xr = __ldcg((const float2*)(gxt + j));
            float2 xz = __ldcg((const float2*)(gxt + H_ + j));
            float2 xn = __ldcg((const float2*)(gxt + 2 * H_ + j));
            float2 hr = make_float2(0.f, 0.f), hz = hr, hn = hr;
#pragma unroll
            for (int s = 0; s < KS; s++) {
                const float* ps = g_part + ((size_t)s * B_ + b) * G_;
                float2 v;
                v = __ldcg((const float2*)(ps + j));          hr.x += v.x; hr.y += v.y;
                v = __ldcg((const float2*)(ps + H_ + j));     hz.x += v.x; hz.y += v.y;
                v = __ldcg((const float2*)(ps + 2 * H_ + j)); hn.x += v.x; hn.y += v.y;
            }
            float2 br = *(const float2*)(bhh + j);
            float2 bz = *(const float2*)(bhh + H_ + j);
            float2 bn = *(const float2*)(bhh + 2 * H_ + j);
            const float* hop = (t == 0) ? h0 : g_h;
            float2 hold = __ldcg((const float2*)(hop + (size_t)b * H_ + j));

            float r0 = 1.f / (1.f + expf(-(xr.x + hr.x + br.x)));
            float z0 = 1.f / (1.f + expf(-(xz.x + hz.x + bz.x)));
            float n0 = tanhf(xn.x + r0 * (hn.x + bn.x));
            float hv0 = (1.f - z0) * n0 + z0 * hold.x;

            float r1 = 1.f / (1.f + expf(-(xr.y + hr.y + br.y)));
            float z1 = 1.f / (1.f + expf(-(xz.y + hz.y + bz.y)));
            float n1 = tanhf(xn.y + r1 * (hn.y + bn.y));
            float hv1 = (1.f - z1) * n1 + z1 * hold.y;

            float2 hnew = make_float2(hv0, hv1);
            *(float2*)(g_h + (size_t)b * H_ + j) = hnew;
            *(float2*)(seqout + ((size_t)t * B_ + b) * H_ + j) = hnew;
            if (t == T_SEQ - 1)
                *(float2*)(hlast + (size_t)b * H_ + j) = hnew;
        }

        grid_barrier(++ph * NBLK);
    }
}

extern "C" void kernel_launch(void* const* d_in, const int* in_sizes, int n_in,
                              void* d_out, int out_size)
{
    const float* x   = (const float*)d_in[0];
    const float* h0  = (const float*)d_in[1];
    const float* Wih = (const float*)d_in[2];
    const float* Whh = (const float*)d_in[3];
    const float* bih = (const float*)d_in[4];
    const float* bhh = (const float*)d_in[5];
    float* out = (float*)d_out;

    cudaFuncSetAttribute(recur, cudaFuncAttributeMaxDynamicSharedMemorySize, SMEMB);

    dim3 ggrid(G_ / 128, (T_SEQ * B_) / 128);
    for (int l = 0; l < L_; l++) {
        const float* a_ext = (l == 0) ? x : nullptr;
        gx_gemm<<<ggrid, 256>>>(a_ext, l == 0 ? 0 : (l == 1 ? 1 : 2),
                                Wih + (size_t)l * G_ * H_, bih + (size_t)l * G_);
        reset_bar<<<1, 1>>>();
        recur<<<NBLK, 256, SMEMB>>>(Whh + (size_t)l * G_ * H_,
                                    bhh + (size_t)l * G_,
                                    h0 + (size_t)l * B_ * H_,
                                    l & 1 ? 1 : 0,
                                    out + (size_t)l * B_ * H_);
    }
}

// round 8
// speedup vs baseline: 1.1047x; 1.1047x over previous
#include <cuda_runtime.h>
#include <cstdint>
#include <math.h>

#define T_SEQ 512
#define B_    64
#define H_    1024
#define G_    3072
#define L_    3
#define NBLK  128
#define CLS   4          // cluster size = K-splits
#define GPB   96         // local gate columns per cluster-group (32 units x 3 gates)
#define KPB   256        // K elements per rank

// dynamic SMEM layout for recur (in 4-byte words):
//   Ws[96][260] tf32, hs[64][260] tf32, part_s[64][100] float
#define WS_W   260
#define HS_OFF (96 * WS_W)
#define PT_OFF (HS_OFF + 64 * WS_W)
#define PT_W   100
#define SMEMB  ((PT_OFF + 64 * PT_W) * 4)   // 192000 B

__device__ float g_gx[(size_t)T_SEQ * B_ * G_];
__device__ float g_seqA[(size_t)T_SEQ * B_ * H_];
__device__ float g_seqB[(size_t)T_SEQ * B_ * H_];
__device__ float g_hbuf[2][B_ * H_];
__device__ unsigned g_bar;

__device__ __forceinline__ unsigned f2tf(float x) {
    unsigned u;
    asm("cvt.rna.tf32.f32 %0, %1;" : "=r"(u) : "f"(x));
    return u;
}

__device__ __forceinline__ void mma_tf32(float* c, const unsigned* a, const unsigned* b) {
    asm volatile(
        "mma.sync.aligned.m16n8k8.row.col.f32.tf32.tf32.f32 "
        "{%0,%1,%2,%3}, {%4,%5,%6,%7}, {%8,%9}, {%0,%1,%2,%3};"
        : "+f"(c[0]), "+f"(c[1]), "+f"(c[2]), "+f"(c[3])
        : "r"(a[0]), "r"(a[1]), "r"(a[2]), "r"(a[3]), "r"(b[0]), "r"(b[1]));
}

__device__ __forceinline__ void grid_barrier(unsigned target) {
    __syncthreads();
    if (threadIdx.x == 0) {
        asm volatile("red.release.gpu.add.u32 [%0], %1;" :: "l"(&g_bar), "r"(1u) : "memory");
        unsigned v;
        do {
            asm volatile("ld.acquire.gpu.u32 %0, [%1];" : "=r"(v) : "l"(&g_bar) : "memory");
        } while (v < target);
    }
    __syncthreads();
}

__global__ void reset_bar() { g_bar = 0u; }

__device__ __forceinline__ uint32_t s2u(const void* p) {
    uint32_t a;
    asm("{ .reg .u64 t; cvta.to.shared.u64 t, %1; cvt.u32.u64 %0, t; }" : "=r"(a) : "l"(p));
    return a;
}

// DSMEM scalar read from cluster rank r at the same SMEM offset
__device__ __forceinline__ float dsmem_ld(uint32_t laddr, uint32_t rank) {
    uint32_t ra; float v;
    asm("mapa.shared::cluster.u32 %0, %1, %2;" : "=r"(ra) : "r"(laddr), "r"(rank));
    asm volatile("ld.shared::cluster.f32 %0, [%1];" : "=f"(v) : "r"(ra) : "memory");
    return v;
}

// ---------------- input-gate GEMM (unchanged, proven ~2us/launch) ----------------
__global__ void __launch_bounds__(256, 2) gx_gemm(
    const float* __restrict__ Aext, int sel,
    const float* __restrict__ W, const float* __restrict__ bias)
{
    const float* A = (sel == 0) ? Aext : (sel == 1 ? g_seqA : g_seqB);
    float* out = g_gx;

    __shared__ unsigned As[16][136];
    __shared__ unsigned Bs[16][136];

    const int tid = threadIdx.x;
    const int mbase = blockIdx.y * 128, nbase = blockIdx.x * 128;
    const int lane = tid & 31, warp = tid >> 5;
    const int wm = (warp >> 2) * 64;
    const int wn = (warp & 3) * 32;
    const int q = lane & 3, g8 = lane >> 2;

    float acc[4][4][4];
#pragma unroll
    for (int i = 0; i < 4; i++)
#pragma unroll
        for (int j = 0; j < 4; j++)
#pragma unroll
            for (int k = 0; k < 4; k++) acc[i][j][k] = 0.f;

    for (int kt = 0; kt < H_; kt += 16) {
        __syncthreads();
#pragma unroll
        for (int r = 0; r < 2; r++) {
            int id = tid + r * 256;
            int row = id >> 2;
            int kc = (id & 3) << 2;
            float4 va = *(const float4*)(A + (size_t)(mbase + row) * H_ + kt + kc);
            As[kc + 0][row] = f2tf(va.x); As[kc + 1][row] = f2tf(va.y);
            As[kc + 2][row] = f2tf(va.z); As[kc + 3][row] = f2tf(va.w);
            float4 vb = *(const float4*)(W + (size_t)(nbase + row) * H_ + kt + kc);
            Bs[kc + 0][row] = f2tf(vb.x); Bs[kc + 1][row] = f2tf(vb.y);
            Bs[kc + 2][row] = f2tf(vb.z); Bs[kc + 3][row] = f2tf(vb.w);
        }
        __syncthreads();
#pragma unroll
        for (int ks = 0; ks < 16; ks += 8) {
            unsigned a[4][4], b[4][2];
#pragma unroll
            for (int mi = 0; mi < 4; mi++) {
                int m0 = wm + mi * 16 + g8;
                a[mi][0] = As[ks + q][m0];
                a[mi][1] = As[ks + q][m0 + 8];
                a[mi][2] = As[ks + 4 + q][m0];
                a[mi][3] = As[ks + 4 + q][m0 + 8];
            }
#pragma unroll
            for (int ni = 0; ni < 4; ni++) {
                int n0 = wn + ni * 8 + g8;
                b[ni][0] = Bs[ks + q][n0];
                b[ni][1] = Bs[ks + 4 + q][n0];
            }
#pragma unroll
            for (int mi = 0; mi < 4; mi++)
#pragma unroll
                for (int ni = 0; ni < 4; ni++)
                    mma_tf32(acc[mi][ni], a[mi], b[ni]);
        }
    }
#pragma unroll
    for (int mi = 0; mi < 4; mi++) {
        int m = mbase + wm + mi * 16 + g8;
#pragma unroll
        for (int ni = 0; ni < 4; ni++) {
            int n = nbase + wn + ni * 8 + 2 * q;
            float b0 = bias[n], b1 = bias[n + 1];
            *(float2*)(out + (size_t)m * G_ + n) =
                make_float2(acc[mi][ni][0] + b0, acc[mi][ni][1] + b1);
            *(float2*)(out + (size_t)(m + 8) * G_ + n) =
                make_float2(acc[mi][ni][2] + b0, acc[mi][ni][3] + b1);
        }
    }
}

// ---------------- persistent recurrence: 32 clusters of 4 (K-split in-cluster) ----------------
extern __shared__ unsigned sh[];

__global__ void __launch_bounds__(256) __cluster_dims__(CLS, 1, 1) recur(
    const float* __restrict__ Whh, const float* __restrict__ bhh,
    const float* __restrict__ h0, int outsel, float* __restrict__ hlast)
{
    unsigned (*Ws)[WS_W] = (unsigned(*)[WS_W])sh;
    unsigned (*hs)[WS_W] = (unsigned(*)[WS_W])(sh + HS_OFF);
    float    (*ps)[PT_W] = (float(*)[PT_W])(sh + PT_OFF);
    float* seqout = outsel ? g_seqB : g_seqA;

    const int tid = threadIdx.x, blk = blockIdx.x;
    const int grp = blk >> 2;          // 0..31 : which 32-hidden-unit group
    const uint32_t rank = blk & 3;     // 0..3  : K-split rank == cluster ctarank
    const int lane = tid & 31, warp = tid >> 5;
    const int q = lane & 3, g8 = lane >> 2;
    const int wm = (warp >> 1) * 16;   // 4 warps in M (64)
    const int wn = (warp & 1) * 48;    // 2 warps in N (96)

    const uint32_t ps_base = s2u(&ps[0][0]);

    // stage W_hh slice -> SMEM tf32, once per layer.
    // local col r = gate*32 + unit  ->  W row = gate*1024 + grp*32 + unit
#pragma unroll
    for (int it = 0; it < 24; it++) {
        int id = tid + it * 256;       // 96 rows x 64 quads
        int r = id >> 6, k = (id & 63) * 4;
        int wrow = (r >> 5) * H_ + grp * 32 + (r & 31);
        float4 v = *(const float4*)(Whh + (size_t)wrow * H_ + rank * KPB + k);
        *(uint4*)&Ws[r][k] = make_uint4(f2tf(v.x), f2tf(v.y), f2tf(v.z), f2tf(v.w));
    }

    unsigned ph = 0;
    for (int t = 0; t < T_SEQ; t++) {
        const int rd = t & 1;
        const float* hsrc = (t == 0) ? h0 : (g_hbuf[rd]);

        // ---- stage h slice [64 x 256] ----
#pragma unroll
        for (int it = 0; it < 16; it++) {
            int id = tid + it * 256;   // 64 rows x 64 quads
            int r = id >> 6, k = (id & 63) * 4;
            float4 v = __ldcg((const float4*)(hsrc + (size_t)r * H_ + rank * KPB + k));
            *(uint4*)&hs[r][k] = make_uint4(f2tf(v.x), f2tf(v.y), f2tf(v.z), f2tf(v.w));
        }
        __syncthreads();

        // ---- GEMM 64x96x256 (proven tiling) ----
        float acc[6][4];
#pragma unroll
        for (int ni = 0; ni < 6; ni++)
#pragma unroll
            for (int k = 0; k < 4; k++) acc[ni][k] = 0.f;

#pragma unroll 4
        for (int kt = 0; kt < KPB; kt += 8) {
            unsigned a[4];
            a[0] = hs[wm + g8][kt + q];
            a[1] = hs[wm + g8 + 8][kt + q];
            a[2] = hs[wm + g8][kt + q + 4];
            a[3] = hs[wm + g8 + 8][kt + q + 4];
#pragma unroll
            for (int ni = 0; ni < 6; ni++) {
                unsigned b[2];
                b[0] = Ws[wn + ni * 8 + g8][kt + q];
                b[1] = Ws[wn + ni * 8 + g8][kt + q + 4];
                mma_tf32(acc[ni], a, b);
            }
        }

        // epilogue -> local SMEM partial tile [64][96]
#pragma unroll
        for (int ni = 0; ni < 6; ni++) {
            int n = wn + ni * 8 + 2 * q;
            int m0 = wm + g8;
            ps[m0][n] = acc[ni][0];     ps[m0][n + 1] = acc[ni][1];
            ps[m0 + 8][n] = acc[ni][2]; ps[m0 + 8][n + 1] = acc[ni][3];
        }

        // cluster barrier: partials visible to all 4 ranks
        asm volatile("barrier.cluster.arrive.aligned;" ::: "memory");
        asm volatile("barrier.cluster.wait.aligned;" ::: "memory");

        // ---- fused reduction + gates for this rank's 8 hidden units ----
        {
            float* hwr = g_hbuf[rd ^ 1];
#pragma unroll
            for (int o = 0; o < 2; o++) {
                int oi = tid + o * 256;          // 0..511
                int b = oi >> 3;                 // batch 0..63
                int ucol = rank * 8 + (oi & 7);  // unit within group: 0..31
                int ghid = grp * 32 + ucol;      // global hidden unit

                float sr = 0.f, sz = 0.f, sn = 0.f;
#pragma unroll
                for (uint32_t r = 0; r < CLS; r++) {
                    uint32_t a0 = ps_base + (uint32_t)(b * PT_W + ucol) * 4u;
                    sr += dsmem_ld(a0, r);
                    sz += dsmem_ld(a0 + 32 * 4, r);
                    sn += dsmem_ld(a0 + 64 * 4, r);
                }

                const float* gxt = g_gx + ((size_t)t * B_ + b) * G_;
                float xr = __ldcg(gxt + ghid);
                float xz = __ldcg(gxt + H_ + ghid);
                float xn = __ldcg(gxt + 2 * H_ + ghid);
                float br = bhh[ghid], bz = bhh[H_ + ghid], bn = bhh[2 * H_ + ghid];
                float hold = (t == 0) ? h0[(size_t)b * H_ + ghid]
                                      : __ldcg(&g_hbuf[rd][(size_t)b * H_ + ghid]);

                float rr = 1.f / (1.f + expf(-(xr + sr + br)));
                float zz = 1.f / (1.f + expf(-(xz + sz + bz)));
                float nn = tanhf(xn + rr * (sn + bn));
                float hv = (1.f - zz) * nn + zz * hold;

                hwr[(size_t)b * H_ + ghid] = hv;
                seqout[((size_t)t * B_ + b) * H_ + ghid] = hv;
                if (t == T_SEQ - 1)
                    hlast[(size_t)b * H_ + ghid] = hv;
            }
        }

        // single grid barrier per step: all h_new visible before next staging
        grid_barrier(++ph * NBLK);
    }
}

extern "C" void kernel_launch(void* const* d_in, const int* in_sizes, int n_in,
                              void* d_out, int out_size)
{
    const float* x   = (const float*)d_in[0];
    const float* h0  = (const float*)d_in[1];
    const float* Wih = (const float*)d_in[2];
    const float* Whh = (const float*)d_in[3];
    const float* bih = (const float*)d_in[4];
    const float* bhh = (const float*)d_in[5];
    float* out = (float*)d_out;

    cudaFuncSetAttribute(recur, cudaFuncAttributeMaxDynamicSharedMemorySize, SMEMB);

    dim3 ggrid(G_ / 128, (T_SEQ * B_) / 128);
    for (int l = 0; l < L_; l++) {
        const float* a_ext = (l == 0) ? x : nullptr;
        gx_gemm<<<ggrid, 256>>>(a_ext, l == 0 ? 0 : (l == 1 ? 1 : 2),
                                Wih + (size_t)l * G_ * H_, bih + (size_t)l * G_);
        reset_bar<<<1, 1>>>();
        recur<<<NBLK, 256, SMEMB>>>(Whh + (size_t)l * G_ * H_,
                                    bhh + (size_t)l * G_,
                                    h0 + (size_t)l * B_ * H_,
                                    l & 1 ? 1 : 0,
                                    out + (size_t)l * B_ * H_);
    }
}